// round 15
// baseline (speedup 1.0000x reference)
#include <cuda_runtime.h>
#include <cstdint>
#include <math.h>

// RZ gate dense matrix, N=12 (confirmed model):
//   output = 16,777,216 float32 (67 MB) = real part of the 4096x4096
//   complex64 matrix; zeros except out[4097*k] = cos(theta/2), k=0..4095.
//   theta = float32 at d_in[0].
//
// Evidence so far: SM-originated stores wall at ~5.0 TB/s (R9/R12/R13);
// memset node path achieves ~6.7 TB/s (R14). This round runs both paths
// CONCURRENTLY on disjoint halves via a forked graph capture:
//   stream 0:  memset [0, S)          then  diag kernel for [0, S)
//   stream s2: SM fill [S, N) with embedded diagonals
// joined with events.

static constexpr long long DIM = 4096;
static constexpr long long DSTRIDE = DIM + 1;      // 4097
static constexpr int BLOCK = 256;
static constexpr int SPAN = 128;                   // floats per fill thread

__global__ void __launch_bounds__(BLOCK)
fill_embed_kernel(const float* __restrict__ theta_p,
                  float* __restrict__ outf,
                  long long base_f, long long end_f) {
    long long t = (long long)blockIdx.x * BLOCK + threadIdx.x;
    long long lo = base_f + t * SPAN;
    if (lo >= end_f) return;
    long long hi = lo + SPAN;
    if (hi > end_f) hi = end_f;

    // base_f and SPAN are multiples of 8 -> lo is 16B aligned.
    float4* g4 = reinterpret_cast<float4*>(outf + lo);
    int n4 = (int)((hi - lo) >> 2);
    const float4 z = make_float4(0.f, 0.f, 0.f, 0.f);
#pragma unroll 8
    for (int j = 0; j < n4; ++j)
        g4[j] = z;
    for (long long j = lo + ((long long)n4 << 2); j < hi; ++j)
        outf[j] = 0.f;   // scalar tail (last thread only, if any)

    // At most one diagonal per 128-float span (stride 4097 > 128).
    long long k = (lo + DSTRIDE - 1) / DSTRIDE;
    long long fidx = k * DSTRIDE;
    if (fidx >= lo && fidx < hi && k < DIM) {
        float theta = theta_p ? theta_p[0] : 0.f;
        if (!isfinite(theta)) theta = 0.f;
        outf[fidx] = cosf(0.5f * theta);   // same thread: ordered after zeros
    }
}

__global__ void rz_diag_kernel(const float* __restrict__ theta_p,
                               float* __restrict__ outf,
                               long long limit_f) {
    long long k = (long long)blockIdx.x * BLOCK + threadIdx.x;
    long long fidx = k * DSTRIDE;
    if (k >= DIM || fidx >= limit_f) return;

    float theta = theta_p ? theta_p[0] : 0.f;
    if (!isfinite(theta)) theta = 0.f;
    outf[fidx] = cosf(0.5f * theta);
}

extern "C" void kernel_launch(void* const* d_in, const int* in_sizes, int n_in,
                              void* d_out, int out_size) {
    const float* theta = (n_in >= 1) ? (const float*)d_in[0] : nullptr;
    float* outf = (float*)d_out;
    long long nfloats = (long long)out_size;       // buffer = out_size*4 bytes

    static cudaStream_t s2 = nullptr;
    static cudaEvent_t ev_fork = nullptr, ev_join = nullptr;
    if (!s2) {
        cudaStreamCreateWithFlags(&s2, cudaStreamNonBlocking);
        cudaEventCreateWithFlags(&ev_fork, cudaEventDisableTiming);
        cudaEventCreateWithFlags(&ev_join, cudaEventDisableTiming);
    }

    // Split: CE path gets ~56% (rate ratio 6.7 : 5.0), multiple of 8 floats.
    long long S = ((nfloats * 56) / 100) & ~7LL;
    if (S < 0) S = 0;
    if (S > nfloats) S = nfloats;

    // Fork: s2 depends on stream-0 state at capture entry.
    cudaEventRecord(ev_fork, 0);
    cudaStreamWaitEvent(s2, ev_fork, 0);

    // Branch A (stream s2): SM fill of [S, nfloats) with embedded diagonals.
    long long fillf = nfloats - S;
    if (fillf > 0) {
        long long threads = (fillf + SPAN - 1) / SPAN;
        int grid = (int)((threads + BLOCK - 1) / BLOCK);
        fill_embed_kernel<<<grid, BLOCK, 0, s2>>>(theta, outf, S, nfloats);
    }

    // Branch B (stream 0): CE memset of [0, S), then its diagonal entries.
    if (S > 0) {
        cudaMemsetAsync(d_out, 0, (size_t)S * 4, 0);
        long long ndiag = (S + DSTRIDE - 1) / DSTRIDE;   // k with 4097k < S
        if (ndiag > DIM) ndiag = DIM;
        int grid = (int)((ndiag + BLOCK - 1) / BLOCK);
        if (grid > 0)
            rz_diag_kernel<<<grid, BLOCK>>>(theta, outf, S);
    }

    // Join: stream 0 waits for branch A.
    cudaEventRecord(ev_join, s2);
    cudaStreamWaitEvent(0, ev_join, 0);
}

// round 16
// speedup vs baseline: 1.1362x; 1.1362x over previous
#include <cuda_runtime.h>
#include <cstdint>
#include <math.h>

// RZ gate dense matrix, N=12 (confirmed model):
//   output = 16,777,216 float32 (67 MB) = real part of the 4096x4096
//   complex64 matrix; zeros except out[4097*k] = cos(theta/2), k=0..4095.
//   theta = float32 at d_in[0].
//
// R14: memset(0) path ~6.7-7 TB/s (likely optimized zero-fill), but serial
// diag kernel costs 4.5us. R15: forked branches DO overlap but share the
// write port. This round: pitched memset2D (pitch = 4097 floats) zeroes all
// NON-diagonal bytes -- diagonal floats live at column 0 of every virtual
// row and are never touched -- so the diag kernel is address-disjoint and
// runs fully in parallel with the fill.

static constexpr long long DIM = 4096;
static constexpr long long DSTRIDE = DIM + 1;      // 4097 floats
static constexpr int BLOCK = 256;

__global__ void rz_diag_kernel(const float* __restrict__ theta_p,
                               float* __restrict__ outf,
                               long long nfloats) {
    long long k = (long long)blockIdx.x * BLOCK + threadIdx.x;
    long long fidx = k * DSTRIDE;
    if (k >= DIM || fidx >= nfloats) return;

    float theta = theta_p ? theta_p[0] : 0.f;
    if (!isfinite(theta)) theta = 0.f;
    outf[fidx] = cosf(0.5f * theta);
}

extern "C" void kernel_launch(void* const* d_in, const int* in_sizes, int n_in,
                              void* d_out, int out_size) {
    const float* theta = (n_in >= 1) ? (const float*)d_in[0] : nullptr;
    float* outf = (float*)d_out;
    long long nfloats = (long long)out_size;       // buffer = out_size*4 bytes

    static cudaStream_t s2 = nullptr;
    static cudaEvent_t ev_fork = nullptr, ev_join = nullptr;
    if (!s2) {
        cudaStreamCreateWithFlags(&s2, cudaStreamNonBlocking);
        cudaEventCreateWithFlags(&ev_fork, cudaEventDisableTiming);
        cudaEventCreateWithFlags(&ev_join, cudaEventDisableTiming);
    }

    // Virtual rows of DSTRIDE floats: row k = [diag float][4096 zero floats].
    // full_rows = #k with 4097k + 4097 <= nfloats.
    long long full_rows = 0;
    if (nfloats >= DSTRIDE)
        full_rows = (nfloats - DSTRIDE) / DSTRIDE + 1;   // rows fully inside
    if (full_rows > DIM) full_rows = DIM;

    // Fork: diag kernel on s2, disjoint from the pitched memset on stream 0.
    cudaEventRecord(ev_fork, 0);
    cudaStreamWaitEvent(s2, ev_fork, 0);

    // Branch A (s2): the 4096 diagonal floats (only bytes memset2D skips).
    rz_diag_kernel<<<(int)((DIM + BLOCK - 1) / BLOCK), BLOCK, 0, s2>>>(
        theta, outf, nfloats);

    // Branch B (stream 0): zero every non-diagonal byte.
    if (full_rows > 0) {
        cudaMemset2DAsync((char*)d_out + 4,             // skip diag float
                          (size_t)DSTRIDE * 4,          // pitch 16388 B
                          0,
                          (size_t)(DSTRIDE - 1) * 4,    // width 16384 B
                          (size_t)full_rows, 0);
    }
    // Tail beyond the last full row (none for the real shape; guard anyway).
    long long tail_start = full_rows * DSTRIDE;          // = nfloats - 1 + 1? ...
    // Skip the diagonal float at tail_start if it exists (kernel writes it).
    if (tail_start < nfloats) {
        long long zfrom = tail_start;
        if (full_rows < DIM && zfrom % DSTRIDE == 0) zfrom += 1;  // diag slot
        if (zfrom < nfloats)
            cudaMemsetAsync((char*)d_out + zfrom * 4, 0,
                            (size_t)(nfloats - zfrom) * 4, 0);
    }

    // Join.
    cudaEventRecord(ev_join, s2);
    cudaStreamWaitEvent(0, ev_join, 0);
}